// round 10
// baseline (speedup 1.0000x reference)
#include <cuda_runtime.h>
#include <cuda_fp16.h>
#include <math.h>

#define TB 256
#define CAP 64                 // per-node bucket capacity (Poisson(16), max ~37)
#define BINSHIFT 8             // bin = dst >> 8 (256 dst nodes per bin)
#define BINCAP 4864            // per-bin capacity (Poisson(4096), 12-sigma headroom)

static const int MAXN = 500000;
static const int MAXE = 8000000;
static const int NBINS = (MAXN + (1 << BINSHIFT) - 1) >> BINSHIFT;   // 1954

// ---- scratch (static __device__ arrays; no allocation) ----
__device__ float2 g_df[MAXN];              // {dinv, dinv/(cnt+1)}
__device__ float4 g_pos4[MAXN];            // padded positions for 1-sector gathers
__device__ uint2  g_xwh[MAXN * 4];         // dinv * (x @ W), fp16: slot k = feats 4k..4k+3
__device__ int2   g_bkt[(size_t)MAXN * CAP]; // (src, ew-as-int) buckets by dst
__device__ int    g_cnt[MAXN];             // in-degree / bucket fill
__device__ int2   g_bin[(size_t)NBINS * BINCAP]; // coarse bins: (src, dst)
__device__ int    g_bincnt[NBINS];
__device__ int    g_is64;

// softplus matching jax.nn.softplus = max(x,0) + log1p(exp(-|x|))
__device__ __forceinline__ float sp(float x) {
    return fmaxf(x, 0.0f) + log1pf(expf(-fabsf(x)));
}

__device__ __forceinline__ uint2 pack4h(float a, float b, float c, float d) {
    __half2 h0 = __floats2half2_rn(a, b);
    __half2 h1 = __floats2half2_rn(c, d);
    uint2 u;
    u.x = *(unsigned*)&h0;
    u.y = *(unsigned*)&h1;
    return u;
}

__device__ __forceinline__ float4 unpack4h(uint2 u) {
    __half2 h0 = *(__half2*)&u.x;
    __half2 h1 = *(__half2*)&u.y;
    float2 f0 = __half22float2(h0);
    float2 f1 = __half22float2(h1);
    return make_float4(f0.x, f0.y, f1.x, f1.y);
}

// ---- detect edge_index dtype ----
__global__ void k_detect(const int* __restrict__ ei_raw) {
    int is64 = 1;
    for (int i = 0; i < 32; i++)
        if (ei_raw[2 * i + 1] != 0) { is64 = 0; break; }
    g_is64 = is64;
}

// ---- zero counters + pad pos to float4 ----
__global__ void k_prep(const float* __restrict__ pos, int N) {
    int n = blockIdx.x * TB + threadIdx.x;
    if (n >= N) return;
    g_cnt[n] = 0;
    if (n < NBINS) g_bincnt[n] = 0;
    g_pos4[n] = make_float4(pos[3 * n + 0], pos[3 * n + 1], pos[3 * n + 2], 0.0f);
}

// ---- pass 1: bin edges by dst>>8; bin tails stay L2-hot -> dense DRAM writes ----
__global__ void k_binscatter(const void* __restrict__ ei_raw, int E) {
    int e = blockIdx.x * TB + threadIdx.x;
    if (e >= E) return;
    int s, d;
    if (g_is64) {
        const long long* ei = (const long long*)ei_raw;
        s = (int)__ldg(&ei[e]);
        d = (int)__ldg(&ei[(long long)E + e]);
    } else {
        const int* ei = (const int*)ei_raw;
        s = __ldg(&ei[e]);
        d = __ldg(&ei[E + e]);
    }
    int bin = d >> BINSHIFT;
    int p = atomicAdd(&g_bincnt[bin], 1);
    if (p < BINCAP)
        g_bin[(size_t)bin * BINCAP + p] = make_int2(s, d);
}

// ---- pass 2: one block per bin; its 256-node dst window is L2-hot ----
__global__ void k_binplace() {
    int bin = blockIdx.x;
    int cnt = g_bincnt[bin];
    if (cnt > BINCAP) cnt = BINCAP;
    size_t base = (size_t)bin * BINCAP;
    for (int i = threadIdx.x; i < cnt; i += TB) {
        int2 sd = g_bin[base + i];
        int p = atomicAdd(&g_cnt[sd.y], 1);
        if (p < CAP)
            ((int*)g_bkt)[2 * ((size_t)sd.y * CAP + p)] = sd.x;  // .y (ew) later
    }
}

// ---- node init: x0 = sp(pos@Wi + bi); xw = x0 @ W_g1 (fp16, unscaled) ----
__global__ void k_node_init(const float* __restrict__ pos,
                            const float* __restrict__ Wi,
                            const float* __restrict__ bi,
                            const float* __restrict__ W1, int N) {
    __shared__ float sWi[48], sbi[16], sW1[256];
    int t = threadIdx.x;
    if (t < 48) sWi[t] = Wi[t];
    if (t < 16) sbi[t] = bi[t];
    sW1[t] = W1[t];
    __syncthreads();
    int n = blockIdx.x * TB + t;
    if (n >= N) return;
    float p0 = pos[3 * n + 0], p1 = pos[3 * n + 1], p2 = pos[3 * n + 2];
    float x[16];
#pragma unroll
    for (int j = 0; j < 16; j++)
        x[j] = sp(fmaf(p0, sWi[j], fmaf(p1, sWi[16 + j], fmaf(p2, sWi[32 + j], sbi[j]))));
    float of[16];
#pragma unroll
    for (int j = 0; j < 16; j++) {
        float acc = 0.0f;
#pragma unroll
        for (int i = 0; i < 16; i++) acc = fmaf(x[i], sW1[i * 16 + j], acc);
        of[j] = acc;
    }
#pragma unroll
    for (int k = 0; k < 4; k++)
        g_xwh[n * 4 + k] = pack4h(of[4 * k], of[4 * k + 1], of[4 * k + 2], of[4 * k + 3]);
}

// ---- per node (quad): edge weights into bucket .y, weighted degree,
//      dinv, scale xwh in place ----
__global__ void k_dinvscale(int N) {
    int tid = blockIdx.x * TB + threadIdx.x;
    int n = tid >> 2;
    int k = tid & 3;
    if (n >= N) return;                 // whole quads exit together
    size_t base = (size_t)n * CAP;
    int cnt = g_cnt[n];
    if (cnt > CAP) cnt = CAP;
    float4 pd = __ldg(&g_pos4[n]);
    float s = 0.0f;
    for (int e = k; e < cnt; e += 4) {
        int src = g_bkt[base + e].x;
        float4 ps = __ldg(&g_pos4[src]);
        float ax = ps.x - pd.x, ay = ps.y - pd.y, az = ps.z - pd.z;
        float ew = sqrtf(ax * ax + ay * ay + az * az);
        ((int*)g_bkt)[2 * (base + e) + 1] = __float_as_int(ew);
        s += ew;
    }
    int lane = threadIdx.x & 31;
    unsigned mask = 0xFu << (lane & ~3);
    s += __shfl_xor_sync(mask, s, 1, 32);
    s += __shfl_xor_sync(mask, s, 2, 32);
    float dinv = rsqrtf(s + 1.0f);      // self-loop weight 1
    if (k == 0)
        g_df[n] = make_float2(dinv, dinv / (float)(cnt + 1));
    float4 v = unpack4h(g_xwh[n * 4 + k]);
    g_xwh[n * 4 + k] = pack4h(dinv * v.x, dinv * v.y, dinv * v.z, dinv * v.w);
}

// ---- aggregate + GCN finalize (4 threads per node). xwh holds dinv*xw. ----
__device__ __forceinline__ float4 agg_finalize(int n, int k, const float* sb) {
    size_t base = (size_t)n * CAP;
    int cnt = g_cnt[n];
    if (cnt > CAP) cnt = CAP;
    float4 acc = unpack4h(g_xwh[n * 4 + k]);   // self term (already dinv-scaled)
#pragma unroll 2
    for (int e = 0; e < cnt; e++) {
        int2 pk = __ldg(&g_bkt[base + e]);
        float ew = __int_as_float(pk.y);
        float4 v = unpack4h(__ldg(&g_xwh[pk.x * 4 + k]));
        acc.x = fmaf(ew, v.x, acc.x);
        acc.y = fmaf(ew, v.y, acc.y);
        acc.z = fmaf(ew, v.z, acc.z);
        acc.w = fmaf(ew, v.w, acc.w);
    }
    float f = __ldg(&g_df[n].y);               // dinv/(cnt+1)
    float4 x;
    x.x = sp(fmaf(f, acc.x, sb[4 * k + 0]));
    x.y = sp(fmaf(f, acc.y, sb[4 * k + 1]));
    x.z = sp(fmaf(f, acc.z, sb[4 * k + 2]));
    x.w = sp(fmaf(f, acc.w, sb[4 * k + 3]));
    return x;
}

// quad 16x16 matmul: x distributed 4 feats/thread -> o distributed 4/thread
__device__ __forceinline__ void quad_matmul(float4 x, const float* sW, int k,
                                            unsigned mask, int qbase, float o[4]) {
    o[0] = o[1] = o[2] = o[3] = 0.0f;
#pragma unroll
    for (int q = 0; q < 4; q++) {
        float4 xq;
        xq.x = __shfl_sync(mask, x.x, qbase + q, 32);
        xq.y = __shfl_sync(mask, x.y, qbase + q, 32);
        xq.z = __shfl_sync(mask, x.z, qbase + q, 32);
        xq.w = __shfl_sync(mask, x.w, qbase + q, 32);
        const float* w0 = &sW[(4 * q + 0) * 16 + 4 * k];
        const float* w1 = &sW[(4 * q + 1) * 16 + 4 * k];
        const float* w2 = &sW[(4 * q + 2) * 16 + 4 * k];
        const float* w3 = &sW[(4 * q + 3) * 16 + 4 * k];
#pragma unroll
        for (int j = 0; j < 4; j++) {
            o[j] = fmaf(xq.x, w0[j], o[j]);
            o[j] = fmaf(xq.y, w1[j], o[j]);
            o[j] = fmaf(xq.z, w2[j], o[j]);
            o[j] = fmaf(xq.w, w3[j], o[j]);
        }
    }
}

// ---- layer 1: aggregate + finalize + matmul W_g2, re-scale by dinv -> xwh ----
__global__ void k_agg1(const float* __restrict__ b1,
                       const float* __restrict__ W2, int N) {
    __shared__ float sb[16], sW[256];
    int t = threadIdx.x;
    if (t < 16) sb[t] = b1[t];
    sW[t] = W2[t];
    __syncthreads();
    int tid = blockIdx.x * TB + t;
    int n = tid >> 2;
    int k = tid & 3;
    if (n >= N) return;
    int lane = t & 31;
    int qbase = lane & ~3;
    unsigned mask = 0xFu << qbase;
    float4 x = agg_finalize(n, k, sb);
    float o[4];
    quad_matmul(x, sW, k, mask, qbase, o);
    float dn = __ldg(&g_df[n].x);
    g_xwh[n * 4 + k] = pack4h(dn * o[0], dn * o[1], dn * o[2], dn * o[3]);
}

// ---- layer 2: aggregate + finalize + MLP (P1,sp,P2) + /sigma -> out ----
__global__ void k_agg2(const float* __restrict__ b2,
                       const float* __restrict__ Wp1,
                       const float* __restrict__ bp1,
                       const float* __restrict__ Wp2,
                       const float* __restrict__ bp2,
                       const float* __restrict__ sig,
                       float* __restrict__ out, int N) {
    __shared__ float sb2[16], sP1[256], sbp1[16], sP2[48], sbp2[3];
    int t = threadIdx.x;
    sP1[t] = Wp1[t];
    if (t < 16) { sb2[t] = b2[t]; sbp1[t] = bp1[t]; }
    if (t < 48) sP2[t] = Wp2[t];
    if (t < 3) sbp2[t] = bp2[t];
    __syncthreads();
    int tid = blockIdx.x * TB + t;
    int n = tid >> 2;
    int k = tid & 3;
    if (n >= N) return;
    int lane = t & 31;
    int qbase = lane & ~3;
    unsigned mask = 0xFu << qbase;
    float4 x = agg_finalize(n, k, sb2);
    float o[4];
    quad_matmul(x, sP1, k, mask, qbase, o);
    float4 y;
    y.x = sp(o[0] + sbp1[4 * k + 0]);
    y.y = sp(o[1] + sbp1[4 * k + 1]);
    y.z = sp(o[2] + sbp1[4 * k + 2]);
    y.w = sp(o[3] + sbp1[4 * k + 3]);
    float sc[3];
#pragma unroll
    for (int j = 0; j < 3; j++) {
        sc[j] = y.x * sP2[(4 * k + 0) * 3 + j]
              + y.y * sP2[(4 * k + 1) * 3 + j]
              + y.z * sP2[(4 * k + 2) * 3 + j]
              + y.w * sP2[(4 * k + 3) * 3 + j];
    }
#pragma unroll
    for (int j = 0; j < 3; j++) {
        sc[j] += __shfl_xor_sync(mask, sc[j], 1, 32);
        sc[j] += __shfl_xor_sync(mask, sc[j], 2, 32);
    }
    if (k == 0) {
        float sgv = __ldg(&sig[n]);
        out[3 * n + 0] = (sc[0] + sbp2[0]) / sgv;
        out[3 * n + 1] = (sc[1] + sbp2[1]) / sgv;
        out[3 * n + 2] = (sc[2] + sbp2[2]) / sgv;
    }
}

extern "C" void kernel_launch(void* const* d_in, const int* in_sizes, int n_in,
                              void* d_out, int out_size) {
    const float* pos    = (const float*)d_in[0];
    const float* sigmas = (const float*)d_in[1];
    const void*  ei     = d_in[2];
    int wbase = (n_in >= 14 || (n_in > 3 && in_sizes[3] == 1)) ? 4 : 3;
    const float* W_init = (const float*)d_in[wbase + 0];
    const float* b_init = (const float*)d_in[wbase + 1];
    const float* W_g1   = (const float*)d_in[wbase + 2];
    const float* b_g1   = (const float*)d_in[wbase + 3];
    const float* W_g2   = (const float*)d_in[wbase + 4];
    const float* b_g2   = (const float*)d_in[wbase + 5];
    const float* W_p1   = (const float*)d_in[wbase + 6];
    const float* b_p1   = (const float*)d_in[wbase + 7];
    const float* W_p2   = (const float*)d_in[wbase + 8];
    const float* b_p2   = (const float*)d_in[wbase + 9];

    int N = in_sizes[0] / 3;
    if (N > MAXN) N = MAXN;
    int E = in_sizes[2] / 2;
    if (E > MAXE) E = MAXE;
    float* out = (float*)d_out;

    int nb_n = (N + TB - 1) / TB;
    int nb_e = (E + TB - 1) / TB;
    int nb_a = (4 * N + TB - 1) / TB;
    int nbins = (N + (1 << BINSHIFT) - 1) >> BINSHIFT;

    // side stream + events (created once on first, uncaptured correctness call)
    static cudaStream_t s2 = nullptr;
    static cudaEvent_t ev_fork = nullptr, ev_join = nullptr;
    if (!s2) {
        cudaStreamCreateWithFlags(&s2, cudaStreamNonBlocking);
        cudaEventCreateWithFlags(&ev_fork, cudaEventDisableTiming);
        cudaEventCreateWithFlags(&ev_join, cudaEventDisableTiming);
    }

    k_detect<<<1, 1>>>((const int*)ei);

    // fork immediately: node_init reads only pos (input) — overlaps edge chain
    cudaEventRecord(ev_fork, 0);
    cudaStreamWaitEvent(s2, ev_fork, 0);
    k_node_init<<<nb_n, TB, 0, s2>>>(pos, W_init, b_init, W_g1, N);
    cudaEventRecord(ev_join, s2);

    // edge chain on main stream
    k_prep<<<nb_n, TB>>>(pos, N);
    k_binscatter<<<nb_e, TB>>>(ei, E);
    k_binplace<<<nbins, TB>>>();

    // join: dinvscale needs buckets (main) and xwh (side)
    cudaStreamWaitEvent(0, ev_join, 0);
    k_dinvscale<<<nb_a, TB>>>(N);
    k_agg1<<<nb_a, TB>>>(b_g1, W_g2, N);
    k_agg2<<<nb_a, TB>>>(b_g2, W_p1, b_p1, W_p2, b_p2, sigmas, out, N);
}

// round 11
// speedup vs baseline: 1.5811x; 1.5811x over previous
#include <cuda_runtime.h>
#include <cuda_fp16.h>
#include <math.h>

#define TB 256
#define CAP 64                 // per-node bucket capacity (Poisson(16), max ~37)
#define BINSHIFT 4             // bin = dst >> 4 (16 dst nodes per bin)
#define BINCAP 512             // per-bin capacity (Poisson(256), 16-sigma headroom)

static const int MAXN = 500000;
static const int MAXE = 8000000;
static const int NBINS = (MAXN + (1 << BINSHIFT) - 1) >> BINSHIFT;   // 31250

// ---- scratch (static __device__ arrays; no allocation) ----
__device__ float2 g_df[MAXN];              // {dinv, dinv/(cnt+1)}
__device__ float4 g_pos4[MAXN];            // padded positions for 1-sector gathers
__device__ uint2  g_xwh[MAXN * 4];         // dinv * (x @ W), fp16: slot k = feats 4k..4k+3
__device__ int2   g_bkt[(size_t)MAXN * CAP]; // (src, ew-as-int) buckets by dst
__device__ int    g_cnt[MAXN];             // in-degree / bucket fill
__device__ unsigned g_bin[(size_t)NBINS * BINCAP]; // packed (src<<4 | dst&15)
__device__ int    g_bincnt[NBINS];
__device__ int    g_is64;

// softplus matching jax.nn.softplus = max(x,0) + log1p(exp(-|x|))
__device__ __forceinline__ float sp(float x) {
    return fmaxf(x, 0.0f) + log1pf(expf(-fabsf(x)));
}

__device__ __forceinline__ uint2 pack4h(float a, float b, float c, float d) {
    __half2 h0 = __floats2half2_rn(a, b);
    __half2 h1 = __floats2half2_rn(c, d);
    uint2 u;
    u.x = *(unsigned*)&h0;
    u.y = *(unsigned*)&h1;
    return u;
}

__device__ __forceinline__ float4 unpack4h(uint2 u) {
    __half2 h0 = *(__half2*)&u.x;
    __half2 h1 = *(__half2*)&u.y;
    float2 f0 = __half22float2(h0);
    float2 f1 = __half22float2(h1);
    return make_float4(f0.x, f0.y, f1.x, f1.y);
}

// ---- detect edge_index dtype ----
__global__ void k_detect(const int* __restrict__ ei_raw) {
    int is64 = 1;
    for (int i = 0; i < 32; i++)
        if (ei_raw[2 * i + 1] != 0) { is64 = 0; break; }
    g_is64 = is64;
}

// ---- zero counters + pad pos to float4 ----
__global__ void k_prep(const float* __restrict__ pos, int N) {
    int n = blockIdx.x * TB + threadIdx.x;
    if (n >= N) return;
    g_cnt[n] = 0;
    if (n < NBINS) g_bincnt[n] = 0;
    g_pos4[n] = make_float4(pos[3 * n + 0], pos[3 * n + 1], pos[3 * n + 2], 0.0f);
}

// ---- pass 1: bin edges by dst>>4; ~256 ops/counter -> low contention;
//      bin tails L2-hot -> dense DRAM writes ----
__global__ void k_binscatter(const void* __restrict__ ei_raw, int E) {
    int e = blockIdx.x * TB + threadIdx.x;
    if (e >= E) return;
    int s, d;
    if (g_is64) {
        const long long* ei = (const long long*)ei_raw;
        s = (int)__ldg(&ei[e]);
        d = (int)__ldg(&ei[(long long)E + e]);
    } else {
        const int* ei = (const int*)ei_raw;
        s = __ldg(&ei[e]);
        d = __ldg(&ei[E + e]);
    }
    int bin = d >> BINSHIFT;
    int p = atomicAdd(&g_bincnt[bin], 1);
    if (p < BINCAP)
        g_bin[(size_t)bin * BINCAP + p] = ((unsigned)s << BINSHIFT) | (unsigned)(d & ((1 << BINSHIFT) - 1));
}

// ---- pass 2: one block per bin; its 16-node window (counters+buckets) L2-hot ----
__global__ void k_binplace() {
    int bin = blockIdx.x;
    int cnt = g_bincnt[bin];
    if (cnt > BINCAP) cnt = BINCAP;
    size_t base = (size_t)bin * BINCAP;
    int dbase = bin << BINSHIFT;
    for (int i = threadIdx.x; i < cnt; i += TB) {
        unsigned v = g_bin[base + i];
        int s = (int)(v >> BINSHIFT);
        int d = dbase | (int)(v & ((1 << BINSHIFT) - 1));
        int p = atomicAdd(&g_cnt[d], 1);
        if (p < CAP)
            ((int*)g_bkt)[2 * ((size_t)d * CAP + p)] = s;   // .y (ew) later
    }
}

// ---- node init: x0 = sp(pos@Wi + bi); xw = x0 @ W_g1 (fp16, unscaled) ----
__global__ void k_node_init(const float* __restrict__ pos,
                            const float* __restrict__ Wi,
                            const float* __restrict__ bi,
                            const float* __restrict__ W1, int N) {
    __shared__ float sWi[48], sbi[16], sW1[256];
    int t = threadIdx.x;
    if (t < 48) sWi[t] = Wi[t];
    if (t < 16) sbi[t] = bi[t];
    sW1[t] = W1[t];
    __syncthreads();
    int n = blockIdx.x * TB + t;
    if (n >= N) return;
    float p0 = pos[3 * n + 0], p1 = pos[3 * n + 1], p2 = pos[3 * n + 2];
    float x[16];
#pragma unroll
    for (int j = 0; j < 16; j++)
        x[j] = sp(fmaf(p0, sWi[j], fmaf(p1, sWi[16 + j], fmaf(p2, sWi[32 + j], sbi[j]))));
    float of[16];
#pragma unroll
    for (int j = 0; j < 16; j++) {
        float acc = 0.0f;
#pragma unroll
        for (int i = 0; i < 16; i++) acc = fmaf(x[i], sW1[i * 16 + j], acc);
        of[j] = acc;
    }
#pragma unroll
    for (int k = 0; k < 4; k++)
        g_xwh[n * 4 + k] = pack4h(of[4 * k], of[4 * k + 1], of[4 * k + 2], of[4 * k + 3]);
}

// ---- per node (quad): edge weights into bucket .y, weighted degree,
//      dinv, scale xwh in place ----
__global__ void k_dinvscale(int N) {
    int tid = blockIdx.x * TB + threadIdx.x;
    int n = tid >> 2;
    int k = tid & 3;
    if (n >= N) return;                 // whole quads exit together
    size_t base = (size_t)n * CAP;
    int cnt = g_cnt[n];
    if (cnt > CAP) cnt = CAP;
    float4 pd = __ldg(&g_pos4[n]);
    float s = 0.0f;
    for (int e = k; e < cnt; e += 4) {
        int src = g_bkt[base + e].x;
        float4 ps = __ldg(&g_pos4[src]);
        float ax = ps.x - pd.x, ay = ps.y - pd.y, az = ps.z - pd.z;
        float ew = sqrtf(ax * ax + ay * ay + az * az);
        ((int*)g_bkt)[2 * (base + e) + 1] = __float_as_int(ew);
        s += ew;
    }
    int lane = threadIdx.x & 31;
    unsigned mask = 0xFu << (lane & ~3);
    s += __shfl_xor_sync(mask, s, 1, 32);
    s += __shfl_xor_sync(mask, s, 2, 32);
    float dinv = rsqrtf(s + 1.0f);      // self-loop weight 1
    if (k == 0)
        g_df[n] = make_float2(dinv, dinv / (float)(cnt + 1));
    float4 v = unpack4h(g_xwh[n * 4 + k]);
    g_xwh[n * 4 + k] = pack4h(dinv * v.x, dinv * v.y, dinv * v.z, dinv * v.w);
}

// ---- aggregate + GCN finalize (4 threads per node). xwh holds dinv*xw. ----
__device__ __forceinline__ float4 agg_finalize(int n, int k, const float* sb) {
    size_t base = (size_t)n * CAP;
    int cnt = g_cnt[n];
    if (cnt > CAP) cnt = CAP;
    float4 acc = unpack4h(g_xwh[n * 4 + k]);   // self term (already dinv-scaled)
#pragma unroll 2
    for (int e = 0; e < cnt; e++) {
        int2 pk = __ldg(&g_bkt[base + e]);
        float ew = __int_as_float(pk.y);
        float4 v = unpack4h(__ldg(&g_xwh[pk.x * 4 + k]));
        acc.x = fmaf(ew, v.x, acc.x);
        acc.y = fmaf(ew, v.y, acc.y);
        acc.z = fmaf(ew, v.z, acc.z);
        acc.w = fmaf(ew, v.w, acc.w);
    }
    float f = __ldg(&g_df[n].y);               // dinv/(cnt+1)
    float4 x;
    x.x = sp(fmaf(f, acc.x, sb[4 * k + 0]));
    x.y = sp(fmaf(f, acc.y, sb[4 * k + 1]));
    x.z = sp(fmaf(f, acc.z, sb[4 * k + 2]));
    x.w = sp(fmaf(f, acc.w, sb[4 * k + 3]));
    return x;
}

// quad 16x16 matmul: x distributed 4 feats/thread -> o distributed 4/thread
__device__ __forceinline__ void quad_matmul(float4 x, const float* sW, int k,
                                            unsigned mask, int qbase, float o[4]) {
    o[0] = o[1] = o[2] = o[3] = 0.0f;
#pragma unroll
    for (int q = 0; q < 4; q++) {
        float4 xq;
        xq.x = __shfl_sync(mask, x.x, qbase + q, 32);
        xq.y = __shfl_sync(mask, x.y, qbase + q, 32);
        xq.z = __shfl_sync(mask, x.z, qbase + q, 32);
        xq.w = __shfl_sync(mask, x.w, qbase + q, 32);
        const float* w0 = &sW[(4 * q + 0) * 16 + 4 * k];
        const float* w1 = &sW[(4 * q + 1) * 16 + 4 * k];
        const float* w2 = &sW[(4 * q + 2) * 16 + 4 * k];
        const float* w3 = &sW[(4 * q + 3) * 16 + 4 * k];
#pragma unroll
        for (int j = 0; j < 4; j++) {
            o[j] = fmaf(xq.x, w0[j], o[j]);
            o[j] = fmaf(xq.y, w1[j], o[j]);
            o[j] = fmaf(xq.z, w2[j], o[j]);
            o[j] = fmaf(xq.w, w3[j], o[j]);
        }
    }
}

// ---- layer 1: aggregate + finalize + matmul W_g2, re-scale by dinv -> xwh ----
__global__ void k_agg1(const float* __restrict__ b1,
                       const float* __restrict__ W2, int N) {
    __shared__ float sb[16], sW[256];
    int t = threadIdx.x;
    if (t < 16) sb[t] = b1[t];
    sW[t] = W2[t];
    __syncthreads();
    int tid = blockIdx.x * TB + t;
    int n = tid >> 2;
    int k = tid & 3;
    if (n >= N) return;
    int lane = t & 31;
    int qbase = lane & ~3;
    unsigned mask = 0xFu << qbase;
    float4 x = agg_finalize(n, k, sb);
    float o[4];
    quad_matmul(x, sW, k, mask, qbase, o);
    float dn = __ldg(&g_df[n].x);
    g_xwh[n * 4 + k] = pack4h(dn * o[0], dn * o[1], dn * o[2], dn * o[3]);
}

// ---- layer 2: aggregate + finalize + MLP (P1,sp,P2) + /sigma -> out ----
__global__ void k_agg2(const float* __restrict__ b2,
                       const float* __restrict__ Wp1,
                       const float* __restrict__ bp1,
                       const float* __restrict__ Wp2,
                       const float* __restrict__ bp2,
                       const float* __restrict__ sig,
                       float* __restrict__ out, int N) {
    __shared__ float sb2[16], sP1[256], sbp1[16], sP2[48], sbp2[3];
    int t = threadIdx.x;
    sP1[t] = Wp1[t];
    if (t < 16) { sb2[t] = b2[t]; sbp1[t] = bp1[t]; }
    if (t < 48) sP2[t] = Wp2[t];
    if (t < 3) sbp2[t] = bp2[t];
    __syncthreads();
    int tid = blockIdx.x * TB + t;
    int n = tid >> 2;
    int k = tid & 3;
    if (n >= N) return;
    int lane = t & 31;
    int qbase = lane & ~3;
    unsigned mask = 0xFu << qbase;
    float4 x = agg_finalize(n, k, sb2);
    float o[4];
    quad_matmul(x, sP1, k, mask, qbase, o);
    float4 y;
    y.x = sp(o[0] + sbp1[4 * k + 0]);
    y.y = sp(o[1] + sbp1[4 * k + 1]);
    y.z = sp(o[2] + sbp1[4 * k + 2]);
    y.w = sp(o[3] + sbp1[4 * k + 3]);
    float sc[3];
#pragma unroll
    for (int j = 0; j < 3; j++) {
        sc[j] = y.x * sP2[(4 * k + 0) * 3 + j]
              + y.y * sP2[(4 * k + 1) * 3 + j]
              + y.z * sP2[(4 * k + 2) * 3 + j]
              + y.w * sP2[(4 * k + 3) * 3 + j];
    }
#pragma unroll
    for (int j = 0; j < 3; j++) {
        sc[j] += __shfl_xor_sync(mask, sc[j], 1, 32);
        sc[j] += __shfl_xor_sync(mask, sc[j], 2, 32);
    }
    if (k == 0) {
        float sgv = __ldg(&sig[n]);
        out[3 * n + 0] = (sc[0] + sbp2[0]) / sgv;
        out[3 * n + 1] = (sc[1] + sbp2[1]) / sgv;
        out[3 * n + 2] = (sc[2] + sbp2[2]) / sgv;
    }
}

extern "C" void kernel_launch(void* const* d_in, const int* in_sizes, int n_in,
                              void* d_out, int out_size) {
    const float* pos    = (const float*)d_in[0];
    const float* sigmas = (const float*)d_in[1];
    const void*  ei     = d_in[2];
    int wbase = (n_in >= 14 || (n_in > 3 && in_sizes[3] == 1)) ? 4 : 3;
    const float* W_init = (const float*)d_in[wbase + 0];
    const float* b_init = (const float*)d_in[wbase + 1];
    const float* W_g1   = (const float*)d_in[wbase + 2];
    const float* b_g1   = (const float*)d_in[wbase + 3];
    const float* W_g2   = (const float*)d_in[wbase + 4];
    const float* b_g2   = (const float*)d_in[wbase + 5];
    const float* W_p1   = (const float*)d_in[wbase + 6];
    const float* b_p1   = (const float*)d_in[wbase + 7];
    const float* W_p2   = (const float*)d_in[wbase + 8];
    const float* b_p2   = (const float*)d_in[wbase + 9];

    int N = in_sizes[0] / 3;
    if (N > MAXN) N = MAXN;
    int E = in_sizes[2] / 2;
    if (E > MAXE) E = MAXE;
    float* out = (float*)d_out;

    int nb_n = (N + TB - 1) / TB;
    int nb_e = (E + TB - 1) / TB;
    int nb_a = (4 * N + TB - 1) / TB;
    int nbins = (N + (1 << BINSHIFT) - 1) >> BINSHIFT;

    // side stream + events (created once on first, uncaptured correctness call)
    static cudaStream_t s2 = nullptr;
    static cudaEvent_t ev_fork = nullptr, ev_join = nullptr;
    if (!s2) {
        cudaStreamCreateWithFlags(&s2, cudaStreamNonBlocking);
        cudaEventCreateWithFlags(&ev_fork, cudaEventDisableTiming);
        cudaEventCreateWithFlags(&ev_join, cudaEventDisableTiming);
    }

    k_detect<<<1, 1>>>((const int*)ei);

    // fork immediately: node_init reads only pos (input) — overlaps edge chain
    cudaEventRecord(ev_fork, 0);
    cudaStreamWaitEvent(s2, ev_fork, 0);
    k_node_init<<<nb_n, TB, 0, s2>>>(pos, W_init, b_init, W_g1, N);
    cudaEventRecord(ev_join, s2);

    // edge chain on main stream
    k_prep<<<nb_n, TB>>>(pos, N);
    k_binscatter<<<nb_e, TB>>>(ei, E);
    k_binplace<<<nbins, TB>>>();

    // join: dinvscale needs buckets (main) and xwh (side)
    cudaStreamWaitEvent(0, ev_join, 0);
    k_dinvscale<<<nb_a, TB>>>(N);
    k_agg1<<<nb_a, TB>>>(b_g1, W_g2, N);
    k_agg2<<<nb_a, TB>>>(b_g2, W_p1, b_p1, W_p2, b_p2, sigmas, out, N);
}

// round 12
// speedup vs baseline: 1.9675x; 1.2444x over previous
#include <cuda_runtime.h>
#include <cuda_fp16.h>
#include <math.h>

#define TB 256
#define CAP 64            // bucket capacity; max degree for Poisson(16) over 500k nodes ~ 37

static const int MAXN = 500000;
static const int MAXE = 8000000;

// ---- scratch (static __device__ arrays; no allocation) ----
__device__ float2 g_df[MAXN];              // {dinv, dinv/(cnt+1)}
__device__ float4 g_pos4[MAXN];            // padded positions for 1-sector gathers
__device__ uint2  g_xwh[MAXN * 4];         // dinv * (x @ W), fp16: slot k = feats 4k..4k+3
__device__ int2   g_bkt[(size_t)MAXN * CAP]; // (src, ew-as-int) buckets by dst
__device__ int    g_cnt[MAXN];             // in-degree / bucket fill
__device__ int    g_is64;

// softplus matching jax.nn.softplus = max(x,0) + log1p(exp(-|x|))
__device__ __forceinline__ float sp(float x) {
    return fmaxf(x, 0.0f) + log1pf(expf(-fabsf(x)));
}

__device__ __forceinline__ uint2 pack4h(float a, float b, float c, float d) {
    __half2 h0 = __floats2half2_rn(a, b);
    __half2 h1 = __floats2half2_rn(c, d);
    uint2 u;
    u.x = *(unsigned*)&h0;
    u.y = *(unsigned*)&h1;
    return u;
}

__device__ __forceinline__ float4 unpack4h(uint2 u) {
    __half2 h0 = *(__half2*)&u.x;
    __half2 h1 = *(__half2*)&u.y;
    float2 f0 = __half22float2(h0);
    float2 f1 = __half22float2(h1);
    return make_float4(f0.x, f0.y, f1.x, f1.y);
}

// ---- detect edge_index dtype ----
__global__ void k_detect(const int* __restrict__ ei_raw) {
    int is64 = 1;
    for (int i = 0; i < 32; i++)
        if (ei_raw[2 * i + 1] != 0) { is64 = 0; break; }
    g_is64 = is64;
}

// ---- zero bucket-fill counters (only thing scatter needs) ----
__global__ void k_zero(int N) {
    int n = blockIdx.x * TB + threadIdx.x;
    if (n < N) g_cnt[n] = 0;
}

// ---- scatter: read edge_index, place src into dst's bucket (counts fused) ----
__global__ void k_scatter(const void* __restrict__ ei_raw, int E) {
    int e = blockIdx.x * TB + threadIdx.x;
    if (e >= E) return;
    int s, d;
    if (g_is64) {
        const long long* ei = (const long long*)ei_raw;
        s = (int)__ldg(&ei[e]);
        d = (int)__ldg(&ei[(long long)E + e]);
    } else {
        const int* ei = (const int*)ei_raw;
        s = __ldg(&ei[e]);
        d = __ldg(&ei[E + e]);
    }
    int p = atomicAdd(&g_cnt[d], 1);
    if (p < CAP)
        ((int*)g_bkt)[2 * ((size_t)d * CAP + p)] = s;   // .y (ew) filled later
}

// ---- node init: pos4 pad + x0 = sp(pos@Wi + bi); xw = x0 @ W_g1 (fp16) ----
__global__ void k_node_init(const float* __restrict__ pos,
                            const float* __restrict__ Wi,
                            const float* __restrict__ bi,
                            const float* __restrict__ W1, int N) {
    __shared__ float sWi[48], sbi[16], sW1[256];
    int t = threadIdx.x;
    if (t < 48) sWi[t] = Wi[t];
    if (t < 16) sbi[t] = bi[t];
    sW1[t] = W1[t];
    __syncthreads();
    int n = blockIdx.x * TB + t;
    if (n >= N) return;
    float p0 = pos[3 * n + 0], p1 = pos[3 * n + 1], p2 = pos[3 * n + 2];
    g_pos4[n] = make_float4(p0, p1, p2, 0.0f);
    float x[16];
#pragma unroll
    for (int j = 0; j < 16; j++)
        x[j] = sp(fmaf(p0, sWi[j], fmaf(p1, sWi[16 + j], fmaf(p2, sWi[32 + j], sbi[j]))));
    float of[16];
#pragma unroll
    for (int j = 0; j < 16; j++) {
        float acc = 0.0f;
#pragma unroll
        for (int i = 0; i < 16; i++) acc = fmaf(x[i], sW1[i * 16 + j], acc);
        of[j] = acc;
    }
#pragma unroll
    for (int k = 0; k < 4; k++)
        g_xwh[n * 4 + k] = pack4h(of[4 * k], of[4 * k + 1], of[4 * k + 2], of[4 * k + 3]);
}

// ---- per node (quad): edge weights into bucket .y (dense int4 RMW),
//      weighted degree, dinv, scale xwh in place ----
__global__ void k_dinvscale(int N) {
    int tid = blockIdx.x * TB + threadIdx.x;
    int n = tid >> 2;
    int k = tid & 3;
    if (n >= N) return;                 // whole quads exit together
    size_t base = (size_t)n * CAP;
    int cnt = g_cnt[n];
    if (cnt > CAP) cnt = CAP;
    float4 pd = __ldg(&g_pos4[n]);
    float s = 0.0f;
    int4* b4 = (int4*)&g_bkt[base];     // 16B aligned (base*8 = n*512)
    int npair = cnt >> 1;
    for (int i = k; i < npair; i += 4) {
        int4 two = b4[i];
        float4 pa = __ldg(&g_pos4[two.x]);
        float ax = pa.x - pd.x, ay = pa.y - pd.y, az = pa.z - pd.z;
        float e0 = sqrtf(ax * ax + ay * ay + az * az);
        float4 pb = __ldg(&g_pos4[two.z]);
        float bx = pb.x - pd.x, by = pb.y - pd.y, bz = pb.z - pd.z;
        float e1 = sqrtf(bx * bx + by * by + bz * bz);
        two.y = __float_as_int(e0);
        two.w = __float_as_int(e1);
        b4[i] = two;                    // dense 16B store
        s += e0 + e1;
    }
    if ((cnt & 1) && k == 3) {          // odd tail entry
        int e = cnt - 1;
        int src = g_bkt[base + e].x;
        float4 pa = __ldg(&g_pos4[src]);
        float ax = pa.x - pd.x, ay = pa.y - pd.y, az = pa.z - pd.z;
        float ew = sqrtf(ax * ax + ay * ay + az * az);
        ((int*)g_bkt)[2 * (base + e) + 1] = __float_as_int(ew);
        s += ew;
    }
    int lane = threadIdx.x & 31;
    unsigned mask = 0xFu << (lane & ~3);
    s += __shfl_xor_sync(mask, s, 1, 32);
    s += __shfl_xor_sync(mask, s, 2, 32);
    float dinv = rsqrtf(s + 1.0f);      // self-loop weight 1
    if (k == 0)
        g_df[n] = make_float2(dinv, dinv / (float)(cnt + 1));
    float4 v = unpack4h(g_xwh[n * 4 + k]);
    g_xwh[n * 4 + k] = pack4h(dinv * v.x, dinv * v.y, dinv * v.z, dinv * v.w);
}

// ---- aggregate + GCN finalize (4 threads per node). xwh holds dinv*xw.
//      int4 bucket loads: 2 edges per load, 4 gathers in flight w/ unroll ----
__device__ __forceinline__ float4 agg_finalize(int n, int k, const float* sb) {
    size_t base = (size_t)n * CAP;
    int cnt = g_cnt[n];
    if (cnt > CAP) cnt = CAP;
    float4 acc = unpack4h(g_xwh[n * 4 + k]);   // self term (already dinv-scaled)
    const int4* b4 = (const int4*)&g_bkt[base];
    int npair = cnt >> 1;
#pragma unroll 2
    for (int i = 0; i < npair; i++) {
        int4 two = __ldg(&b4[i]);
        float4 v0 = unpack4h(__ldg(&g_xwh[two.x * 4 + k]));
        float4 v1 = unpack4h(__ldg(&g_xwh[two.z * 4 + k]));
        float e0 = __int_as_float(two.y);
        float e1 = __int_as_float(two.w);
        acc.x = fmaf(e0, v0.x, fmaf(e1, v1.x, acc.x));
        acc.y = fmaf(e0, v0.y, fmaf(e1, v1.y, acc.y));
        acc.z = fmaf(e0, v0.z, fmaf(e1, v1.z, acc.z));
        acc.w = fmaf(e0, v0.w, fmaf(e1, v1.w, acc.w));
    }
    if (cnt & 1) {
        int2 pk = __ldg(&g_bkt[base + cnt - 1]);
        float ew = __int_as_float(pk.y);
        float4 v = unpack4h(__ldg(&g_xwh[pk.x * 4 + k]));
        acc.x = fmaf(ew, v.x, acc.x);
        acc.y = fmaf(ew, v.y, acc.y);
        acc.z = fmaf(ew, v.z, acc.z);
        acc.w = fmaf(ew, v.w, acc.w);
    }
    float f = __ldg(&g_df[n].y);               // dinv/(cnt+1)
    float4 x;
    x.x = sp(fmaf(f, acc.x, sb[4 * k + 0]));
    x.y = sp(fmaf(f, acc.y, sb[4 * k + 1]));
    x.z = sp(fmaf(f, acc.z, sb[4 * k + 2]));
    x.w = sp(fmaf(f, acc.w, sb[4 * k + 3]));
    return x;
}

// quad 16x16 matmul: x distributed 4 feats/thread -> o distributed 4/thread
__device__ __forceinline__ void quad_matmul(float4 x, const float* sW, int k,
                                            unsigned mask, int qbase, float o[4]) {
    o[0] = o[1] = o[2] = o[3] = 0.0f;
#pragma unroll
    for (int q = 0; q < 4; q++) {
        float4 xq;
        xq.x = __shfl_sync(mask, x.x, qbase + q, 32);
        xq.y = __shfl_sync(mask, x.y, qbase + q, 32);
        xq.z = __shfl_sync(mask, x.z, qbase + q, 32);
        xq.w = __shfl_sync(mask, x.w, qbase + q, 32);
        const float* w0 = &sW[(4 * q + 0) * 16 + 4 * k];
        const float* w1 = &sW[(4 * q + 1) * 16 + 4 * k];
        const float* w2 = &sW[(4 * q + 2) * 16 + 4 * k];
        const float* w3 = &sW[(4 * q + 3) * 16 + 4 * k];
#pragma unroll
        for (int j = 0; j < 4; j++) {
            o[j] = fmaf(xq.x, w0[j], o[j]);
            o[j] = fmaf(xq.y, w1[j], o[j]);
            o[j] = fmaf(xq.z, w2[j], o[j]);
            o[j] = fmaf(xq.w, w3[j], o[j]);
        }
    }
}

// ---- layer 1: aggregate + finalize + matmul W_g2, re-scale by dinv -> xwh ----
__global__ void k_agg1(const float* __restrict__ b1,
                       const float* __restrict__ W2, int N) {
    __shared__ float sb[16], sW[256];
    int t = threadIdx.x;
    if (t < 16) sb[t] = b1[t];
    sW[t] = W2[t];
    __syncthreads();
    int tid = blockIdx.x * TB + t;
    int n = tid >> 2;
    int k = tid & 3;
    if (n >= N) return;
    int lane = t & 31;
    int qbase = lane & ~3;
    unsigned mask = 0xFu << qbase;
    float4 x = agg_finalize(n, k, sb);
    float o[4];
    quad_matmul(x, sW, k, mask, qbase, o);
    float dn = __ldg(&g_df[n].x);
    g_xwh[n * 4 + k] = pack4h(dn * o[0], dn * o[1], dn * o[2], dn * o[3]);
}

// ---- layer 2: aggregate + finalize + MLP (P1,sp,P2) + /sigma -> out ----
__global__ void k_agg2(const float* __restrict__ b2,
                       const float* __restrict__ Wp1,
                       const float* __restrict__ bp1,
                       const float* __restrict__ Wp2,
                       const float* __restrict__ bp2,
                       const float* __restrict__ sig,
                       float* __restrict__ out, int N) {
    __shared__ float sb2[16], sP1[256], sbp1[16], sP2[48], sbp2[3];
    int t = threadIdx.x;
    sP1[t] = Wp1[t];
    if (t < 16) { sb2[t] = b2[t]; sbp1[t] = bp1[t]; }
    if (t < 48) sP2[t] = Wp2[t];
    if (t < 3) sbp2[t] = bp2[t];
    __syncthreads();
    int tid = blockIdx.x * TB + t;
    int n = tid >> 2;
    int k = tid & 3;
    if (n >= N) return;
    int lane = t & 31;
    int qbase = lane & ~3;
    unsigned mask = 0xFu << qbase;
    float4 x = agg_finalize(n, k, sb2);
    float o[4];
    quad_matmul(x, sP1, k, mask, qbase, o);
    float4 y;
    y.x = sp(o[0] + sbp1[4 * k + 0]);
    y.y = sp(o[1] + sbp1[4 * k + 1]);
    y.z = sp(o[2] + sbp1[4 * k + 2]);
    y.w = sp(o[3] + sbp1[4 * k + 3]);
    float sc[3];
#pragma unroll
    for (int j = 0; j < 3; j++) {
        sc[j] = y.x * sP2[(4 * k + 0) * 3 + j]
              + y.y * sP2[(4 * k + 1) * 3 + j]
              + y.z * sP2[(4 * k + 2) * 3 + j]
              + y.w * sP2[(4 * k + 3) * 3 + j];
    }
#pragma unroll
    for (int j = 0; j < 3; j++) {
        sc[j] += __shfl_xor_sync(mask, sc[j], 1, 32);
        sc[j] += __shfl_xor_sync(mask, sc[j], 2, 32);
    }
    if (k == 0) {
        float sgv = __ldg(&sig[n]);
        out[3 * n + 0] = (sc[0] + sbp2[0]) / sgv;
        out[3 * n + 1] = (sc[1] + sbp2[1]) / sgv;
        out[3 * n + 2] = (sc[2] + sbp2[2]) / sgv;
    }
}

extern "C" void kernel_launch(void* const* d_in, const int* in_sizes, int n_in,
                              void* d_out, int out_size) {
    const float* pos    = (const float*)d_in[0];
    const float* sigmas = (const float*)d_in[1];
    const void*  ei     = d_in[2];
    int wbase = (n_in >= 14 || (n_in > 3 && in_sizes[3] == 1)) ? 4 : 3;
    const float* W_init = (const float*)d_in[wbase + 0];
    const float* b_init = (const float*)d_in[wbase + 1];
    const float* W_g1   = (const float*)d_in[wbase + 2];
    const float* b_g1   = (const float*)d_in[wbase + 3];
    const float* W_g2   = (const float*)d_in[wbase + 4];
    const float* b_g2   = (const float*)d_in[wbase + 5];
    const float* W_p1   = (const float*)d_in[wbase + 6];
    const float* b_p1   = (const float*)d_in[wbase + 7];
    const float* W_p2   = (const float*)d_in[wbase + 8];
    const float* b_p2   = (const float*)d_in[wbase + 9];

    int N = in_sizes[0] / 3;
    if (N > MAXN) N = MAXN;
    int E = in_sizes[2] / 2;
    if (E > MAXE) E = MAXE;
    float* out = (float*)d_out;

    int nb_n = (N + TB - 1) / TB;
    int nb_e = (E + TB - 1) / TB;
    int nb_a = (4 * N + TB - 1) / TB;

    // side stream + events (created once on first, uncaptured correctness call)
    static cudaStream_t s2 = nullptr;
    static cudaEvent_t ev_fork = nullptr, ev_join = nullptr;
    if (!s2) {
        cudaStreamCreateWithFlags(&s2, cudaStreamNonBlocking);
        cudaEventCreateWithFlags(&ev_fork, cudaEventDisableTiming);
        cudaEventCreateWithFlags(&ev_join, cudaEventDisableTiming);
    }

    k_detect<<<1, 1>>>((const int*)ei);

    // fork immediately: node_init reads only pos (input) — overlaps edge chain
    cudaEventRecord(ev_fork, 0);
    cudaStreamWaitEvent(s2, ev_fork, 0);
    k_node_init<<<nb_n, TB, 0, s2>>>(pos, W_init, b_init, W_g1, N);
    cudaEventRecord(ev_join, s2);

    // edge chain on main stream
    k_zero<<<nb_n, TB>>>(N);
    k_scatter<<<nb_e, TB>>>(ei, E);

    // join: dinvscale needs buckets (main) and xwh+pos4 (side)
    cudaStreamWaitEvent(0, ev_join, 0);
    k_dinvscale<<<nb_a, TB>>>(N);
    k_agg1<<<nb_a, TB>>>(b_g1, W_g2, N);
    k_agg2<<<nb_a, TB>>>(b_g2, W_p1, b_p1, W_p2, b_p2, sigmas, out, N);
}

// round 13
// speedup vs baseline: 1.9841x; 1.0084x over previous
#include <cuda_runtime.h>
#include <cuda_fp16.h>
#include <math.h>

#define TB 256
#define CAP 48            // bucket capacity; Poisson(16) max ~37, P(>48)~1e-9/node

static const int MAXN = 500000;
static const int MAXE = 8000000;

// ---- scratch (static __device__ arrays; no allocation) ----
__device__ float2 g_df[MAXN];              // {dinv, dinv/(cnt+1)}
__device__ float4 g_pos4[MAXN];            // padded positions for 1-sector gathers
__device__ uint2  g_xwh[MAXN * 4];         // dinv * (x @ W), fp16: slot k = feats 4k..4k+3
__device__ int    g_bsrc[(size_t)MAXN * CAP]; // src indices, bucketed by dst (96MB — L2-resident)
__device__ float  g_bew[(size_t)MAXN * CAP];  // edge weights (filled by dinvscale)
__device__ int    g_cnt[MAXN];             // in-degree / bucket fill
__device__ int    g_is64;

// softplus matching jax.nn.softplus = max(x,0) + log1p(exp(-|x|))
__device__ __forceinline__ float sp(float x) {
    return fmaxf(x, 0.0f) + log1pf(expf(-fabsf(x)));
}

__device__ __forceinline__ uint2 pack4h(float a, float b, float c, float d) {
    __half2 h0 = __floats2half2_rn(a, b);
    __half2 h1 = __floats2half2_rn(c, d);
    uint2 u;
    u.x = *(unsigned*)&h0;
    u.y = *(unsigned*)&h1;
    return u;
}

__device__ __forceinline__ float4 unpack4h(uint2 u) {
    __half2 h0 = *(__half2*)&u.x;
    __half2 h1 = *(__half2*)&u.y;
    float2 f0 = __half22float2(h0);
    float2 f1 = __half22float2(h1);
    return make_float4(f0.x, f0.y, f1.x, f1.y);
}

// ---- detect edge_index dtype ----
__global__ void k_detect(const int* __restrict__ ei_raw) {
    int is64 = 1;
    for (int i = 0; i < 32; i++)
        if (ei_raw[2 * i + 1] != 0) { is64 = 0; break; }
    g_is64 = is64;
}

// ---- zero bucket-fill counters ----
__global__ void k_zero(int N) {
    int n = blockIdx.x * TB + threadIdx.x;
    if (n < N) g_cnt[n] = 0;
}

// ---- scatter: place src into dst's bucket; touches only the 96MB src array ----
__global__ void k_scatter(const void* __restrict__ ei_raw, int E) {
    int e = blockIdx.x * TB + threadIdx.x;
    if (e >= E) return;
    int s, d;
    if (g_is64) {
        const long long* ei = (const long long*)ei_raw;
        s = (int)__ldg(&ei[e]);
        d = (int)__ldg(&ei[(long long)E + e]);
    } else {
        const int* ei = (const int*)ei_raw;
        s = __ldg(&ei[e]);
        d = __ldg(&ei[E + e]);
    }
    int p = atomicAdd(&g_cnt[d], 1);
    if (p < CAP)
        g_bsrc[(size_t)d * CAP + p] = s;
}

// ---- node init: pos4 pad + x0 = sp(pos@Wi + bi); xw = x0 @ W_g1 (fp16) ----
__global__ void k_node_init(const float* __restrict__ pos,
                            const float* __restrict__ Wi,
                            const float* __restrict__ bi,
                            const float* __restrict__ W1, int N) {
    __shared__ float sWi[48], sbi[16], sW1[256];
    int t = threadIdx.x;
    if (t < 48) sWi[t] = Wi[t];
    if (t < 16) sbi[t] = bi[t];
    sW1[t] = W1[t];
    __syncthreads();
    int n = blockIdx.x * TB + t;
    if (n >= N) return;
    float p0 = pos[3 * n + 0], p1 = pos[3 * n + 1], p2 = pos[3 * n + 2];
    g_pos4[n] = make_float4(p0, p1, p2, 0.0f);
    float x[16];
#pragma unroll
    for (int j = 0; j < 16; j++)
        x[j] = sp(fmaf(p0, sWi[j], fmaf(p1, sWi[16 + j], fmaf(p2, sWi[32 + j], sbi[j]))));
    float of[16];
#pragma unroll
    for (int j = 0; j < 16; j++) {
        float acc = 0.0f;
#pragma unroll
        for (int i = 0; i < 16; i++) acc = fmaf(x[i], sW1[i * 16 + j], acc);
        of[j] = acc;
    }
#pragma unroll
    for (int k = 0; k < 4; k++)
        g_xwh[n * 4 + k] = pack4h(of[4 * k], of[4 * k + 1], of[4 * k + 2], of[4 * k + 3]);
}

// ---- per node (quad): compute edge weights into g_bew (dense float4 stores),
//      weighted degree, dinv, scale xwh in place ----
__global__ void k_dinvscale(int N) {
    int tid = blockIdx.x * TB + threadIdx.x;
    int n = tid >> 2;
    int k = tid & 3;
    if (n >= N) return;                 // whole quads exit together
    size_t base = (size_t)n * CAP;
    int cnt = g_cnt[n];
    if (cnt > CAP) cnt = CAP;
    float4 pd = __ldg(&g_pos4[n]);
    const int4* s4 = (const int4*)&g_bsrc[base];   // base*4 = n*192, 16B aligned
    float4* e4 = (float4*)&g_bew[base];
    float s = 0.0f;
    int ngq = (cnt + 3) >> 2;           // groups of 4 edges
    for (int g = k; g < ngq; g += 4) {
        int4 ss = __ldg(&s4[g]);
        int rem = cnt - (g << 2);
        float4 ee = make_float4(0.0f, 0.0f, 0.0f, 0.0f);
        const int idx[4] = {ss.x, ss.y, ss.z, ss.w};
        float* ep = (float*)&ee;
#pragma unroll
        for (int j = 0; j < 4; j++) {
            if (j < rem) {
                float4 pa = __ldg(&g_pos4[idx[j]]);
                float ax = pa.x - pd.x, ay = pa.y - pd.y, az = pa.z - pd.z;
                float ew = sqrtf(ax * ax + ay * ay + az * az);
                ep[j] = ew;
                s += ew;
            }
        }
        e4[g] = ee;                     // dense 16B store
    }
    int lane = threadIdx.x & 31;
    unsigned mask = 0xFu << (lane & ~3);
    s += __shfl_xor_sync(mask, s, 1, 32);
    s += __shfl_xor_sync(mask, s, 2, 32);
    float dinv = rsqrtf(s + 1.0f);      // self-loop weight 1
    if (k == 0)
        g_df[n] = make_float2(dinv, dinv / (float)(cnt + 1));
    float4 v = unpack4h(g_xwh[n * 4 + k]);
    g_xwh[n * 4 + k] = pack4h(dinv * v.x, dinv * v.y, dinv * v.z, dinv * v.w);
}

// ---- aggregate + GCN finalize (4 threads per node). xwh holds dinv*xw.
//      int4+float4 loads: 4 edges per load pair ----
__device__ __forceinline__ float4 agg_finalize(int n, int k, const float* sb) {
    size_t base = (size_t)n * CAP;
    int cnt = g_cnt[n];
    if (cnt > CAP) cnt = CAP;
    float4 acc = unpack4h(g_xwh[n * 4 + k]);   // self term (already dinv-scaled)
    const int4* s4 = (const int4*)&g_bsrc[base];
    const float4* e4 = (const float4*)&g_bew[base];
    int nq = cnt >> 2;
    for (int i = 0; i < nq; i++) {
        int4 ss = __ldg(&s4[i]);
        float4 ee = __ldg(&e4[i]);
        float4 v0 = unpack4h(__ldg(&g_xwh[ss.x * 4 + k]));
        float4 v1 = unpack4h(__ldg(&g_xwh[ss.y * 4 + k]));
        float4 v2 = unpack4h(__ldg(&g_xwh[ss.z * 4 + k]));
        float4 v3 = unpack4h(__ldg(&g_xwh[ss.w * 4 + k]));
        acc.x = fmaf(ee.x, v0.x, fmaf(ee.y, v1.x, fmaf(ee.z, v2.x, fmaf(ee.w, v3.x, acc.x))));
        acc.y = fmaf(ee.x, v0.y, fmaf(ee.y, v1.y, fmaf(ee.z, v2.y, fmaf(ee.w, v3.y, acc.y))));
        acc.z = fmaf(ee.x, v0.z, fmaf(ee.y, v1.z, fmaf(ee.z, v2.z, fmaf(ee.w, v3.z, acc.z))));
        acc.w = fmaf(ee.x, v0.w, fmaf(ee.y, v1.w, fmaf(ee.z, v2.w, fmaf(ee.w, v3.w, acc.w))));
    }
    for (int e = nq << 2; e < cnt; e++) {
        int src = __ldg(&g_bsrc[base + e]);
        float ew = __ldg(&g_bew[base + e]);
        float4 v = unpack4h(__ldg(&g_xwh[src * 4 + k]));
        acc.x = fmaf(ew, v.x, acc.x);
        acc.y = fmaf(ew, v.y, acc.y);
        acc.z = fmaf(ew, v.z, acc.z);
        acc.w = fmaf(ew, v.w, acc.w);
    }
    float f = __ldg(&g_df[n].y);               // dinv/(cnt+1)
    float4 x;
    x.x = sp(fmaf(f, acc.x, sb[4 * k + 0]));
    x.y = sp(fmaf(f, acc.y, sb[4 * k + 1]));
    x.z = sp(fmaf(f, acc.z, sb[4 * k + 2]));
    x.w = sp(fmaf(f, acc.w, sb[4 * k + 3]));
    return x;
}

// quad 16x16 matmul: x distributed 4 feats/thread -> o distributed 4/thread
__device__ __forceinline__ void quad_matmul(float4 x, const float* sW, int k,
                                            unsigned mask, int qbase, float o[4]) {
    o[0] = o[1] = o[2] = o[3] = 0.0f;
#pragma unroll
    for (int q = 0; q < 4; q++) {
        float4 xq;
        xq.x = __shfl_sync(mask, x.x, qbase + q, 32);
        xq.y = __shfl_sync(mask, x.y, qbase + q, 32);
        xq.z = __shfl_sync(mask, x.z, qbase + q, 32);
        xq.w = __shfl_sync(mask, x.w, qbase + q, 32);
        const float* w0 = &sW[(4 * q + 0) * 16 + 4 * k];
        const float* w1 = &sW[(4 * q + 1) * 16 + 4 * k];
        const float* w2 = &sW[(4 * q + 2) * 16 + 4 * k];
        const float* w3 = &sW[(4 * q + 3) * 16 + 4 * k];
#pragma unroll
        for (int j = 0; j < 4; j++) {
            o[j] = fmaf(xq.x, w0[j], o[j]);
            o[j] = fmaf(xq.y, w1[j], o[j]);
            o[j] = fmaf(xq.z, w2[j], o[j]);
            o[j] = fmaf(xq.w, w3[j], o[j]);
        }
    }
}

// ---- layer 1: aggregate + finalize + matmul W_g2, re-scale by dinv -> xwh ----
__global__ void k_agg1(const float* __restrict__ b1,
                       const float* __restrict__ W2, int N) {
    __shared__ float sb[16], sW[256];
    int t = threadIdx.x;
    if (t < 16) sb[t] = b1[t];
    sW[t] = W2[t];
    __syncthreads();
    int tid = blockIdx.x * TB + t;
    int n = tid >> 2;
    int k = tid & 3;
    if (n >= N) return;
    int lane = t & 31;
    int qbase = lane & ~3;
    unsigned mask = 0xFu << qbase;
    float4 x = agg_finalize(n, k, sb);
    float o[4];
    quad_matmul(x, sW, k, mask, qbase, o);
    float dn = __ldg(&g_df[n].x);
    g_xwh[n * 4 + k] = pack4h(dn * o[0], dn * o[1], dn * o[2], dn * o[3]);
}

// ---- layer 2: aggregate + finalize + MLP (P1,sp,P2) + /sigma -> out ----
__global__ void k_agg2(const float* __restrict__ b2,
                       const float* __restrict__ Wp1,
                       const float* __restrict__ bp1,
                       const float* __restrict__ Wp2,
                       const float* __restrict__ bp2,
                       const float* __restrict__ sig,
                       float* __restrict__ out, int N) {
    __shared__ float sb2[16], sP1[256], sbp1[16], sP2[48], sbp2[3];
    int t = threadIdx.x;
    sP1[t] = Wp1[t];
    if (t < 16) { sb2[t] = b2[t]; sbp1[t] = bp1[t]; }
    if (t < 48) sP2[t] = Wp2[t];
    if (t < 3) sbp2[t] = bp2[t];
    __syncthreads();
    int tid = blockIdx.x * TB + t;
    int n = tid >> 2;
    int k = tid & 3;
    if (n >= N) return;
    int lane = t & 31;
    int qbase = lane & ~3;
    unsigned mask = 0xFu << qbase;
    float4 x = agg_finalize(n, k, sb2);
    float o[4];
    quad_matmul(x, sP1, k, mask, qbase, o);
    float4 y;
    y.x = sp(o[0] + sbp1[4 * k + 0]);
    y.y = sp(o[1] + sbp1[4 * k + 1]);
    y.z = sp(o[2] + sbp1[4 * k + 2]);
    y.w = sp(o[3] + sbp1[4 * k + 3]);
    float sc[3];
#pragma unroll
    for (int j = 0; j < 3; j++) {
        sc[j] = y.x * sP2[(4 * k + 0) * 3 + j]
              + y.y * sP2[(4 * k + 1) * 3 + j]
              + y.z * sP2[(4 * k + 2) * 3 + j]
              + y.w * sP2[(4 * k + 3) * 3 + j];
    }
#pragma unroll
    for (int j = 0; j < 3; j++) {
        sc[j] += __shfl_xor_sync(mask, sc[j], 1, 32);
        sc[j] += __shfl_xor_sync(mask, sc[j], 2, 32);
    }
    if (k == 0) {
        float sgv = __ldg(&sig[n]);
        out[3 * n + 0] = (sc[0] + sbp2[0]) / sgv;
        out[3 * n + 1] = (sc[1] + sbp2[1]) / sgv;
        out[3 * n + 2] = (sc[2] + sbp2[2]) / sgv;
    }
}

extern "C" void kernel_launch(void* const* d_in, const int* in_sizes, int n_in,
                              void* d_out, int out_size) {
    const float* pos    = (const float*)d_in[0];
    const float* sigmas = (const float*)d_in[1];
    const void*  ei     = d_in[2];
    int wbase = (n_in >= 14 || (n_in > 3 && in_sizes[3] == 1)) ? 4 : 3;
    const float* W_init = (const float*)d_in[wbase + 0];
    const float* b_init = (const float*)d_in[wbase + 1];
    const float* W_g1   = (const float*)d_in[wbase + 2];
    const float* b_g1   = (const float*)d_in[wbase + 3];
    const float* W_g2   = (const float*)d_in[wbase + 4];
    const float* b_g2   = (const float*)d_in[wbase + 5];
    const float* W_p1   = (const float*)d_in[wbase + 6];
    const float* b_p1   = (const float*)d_in[wbase + 7];
    const float* W_p2   = (const float*)d_in[wbase + 8];
    const float* b_p2   = (const float*)d_in[wbase + 9];

    int N = in_sizes[0] / 3;
    if (N > MAXN) N = MAXN;
    int E = in_sizes[2] / 2;
    if (E > MAXE) E = MAXE;
    float* out = (float*)d_out;

    int nb_n = (N + TB - 1) / TB;
    int nb_e = (E + TB - 1) / TB;
    int nb_a = (4 * N + TB - 1) / TB;

    // side stream + events (created once on first, uncaptured correctness call)
    static cudaStream_t s2 = nullptr;
    static cudaEvent_t ev_fork = nullptr, ev_join = nullptr;
    if (!s2) {
        cudaStreamCreateWithFlags(&s2, cudaStreamNonBlocking);
        cudaEventCreateWithFlags(&ev_fork, cudaEventDisableTiming);
        cudaEventCreateWithFlags(&ev_join, cudaEventDisableTiming);
    }

    k_detect<<<1, 1>>>((const int*)ei);

    // fork immediately: node_init reads only pos (input) — overlaps edge chain
    cudaEventRecord(ev_fork, 0);
    cudaStreamWaitEvent(s2, ev_fork, 0);
    k_node_init<<<nb_n, TB, 0, s2>>>(pos, W_init, b_init, W_g1, N);
    cudaEventRecord(ev_join, s2);

    // edge chain on main stream
    k_zero<<<nb_n, TB>>>(N);
    k_scatter<<<nb_e, TB>>>(ei, E);

    // join: dinvscale needs buckets (main) and xwh+pos4 (side)
    cudaStreamWaitEvent(0, ev_join, 0);
    k_dinvscale<<<nb_a, TB>>>(N);
    k_agg1<<<nb_a, TB>>>(b_g1, W_g2, N);
    k_agg2<<<nb_a, TB>>>(b_g2, W_p1, b_p1, W_p2, b_p2, sigmas, out, N);
}

// round 14
// speedup vs baseline: 2.0049x; 1.0105x over previous
#include <cuda_runtime.h>
#include <cuda_fp16.h>
#include <math.h>

#define TB 256
#define CAP 48            // bucket capacity; Poisson(16) max ~37, P(>48)~1e-9/node

static const int MAXN = 500000;
static const int MAXE = 8000000;

// ---- scratch (static __device__ arrays; no allocation) ----
__device__ float2 g_df[MAXN];              // {dinv, dinv/(cnt+1)}
__device__ float4 g_pos4[MAXN];            // padded positions for 1-sector gathers
__device__ uint2  g_xwh[MAXN * 4];         // dinv * (x @ W), fp16: slot k = feats 4k..4k+3
__device__ int    g_bsrc[(size_t)MAXN * CAP]; // src indices, bucketed by dst (96MB — L2-resident)
__device__ float  g_bew[(size_t)MAXN * CAP];  // edge weights (filled by dinvscale)
__device__ int    g_cnt[MAXN];             // in-degree / bucket fill
__device__ int    g_is64;

// softplus matching jax.nn.softplus = max(x,0) + log1p(exp(-|x|))
__device__ __forceinline__ float sp(float x) {
    return fmaxf(x, 0.0f) + log1pf(expf(-fabsf(x)));
}

__device__ __forceinline__ uint2 pack4h(float a, float b, float c, float d) {
    __half2 h0 = __floats2half2_rn(a, b);
    __half2 h1 = __floats2half2_rn(c, d);
    uint2 u;
    u.x = *(unsigned*)&h0;
    u.y = *(unsigned*)&h1;
    return u;
}

__device__ __forceinline__ float4 unpack4h(uint2 u) {
    __half2 h0 = *(__half2*)&u.x;
    __half2 h1 = *(__half2*)&u.y;
    float2 f0 = __half22float2(h0);
    float2 f1 = __half22float2(h1);
    return make_float4(f0.x, f0.y, f1.x, f1.y);
}

// ---- detect edge_index dtype ----
__global__ void k_detect(const int* __restrict__ ei_raw) {
    int is64 = 1;
    for (int i = 0; i < 32; i++)
        if (ei_raw[2 * i + 1] != 0) { is64 = 0; break; }
    g_is64 = is64;
}

// ---- zero bucket-fill counters ----
__global__ void k_zero(int N) {
    int n = blockIdx.x * TB + threadIdx.x;
    if (n < N) g_cnt[n] = 0;
}

// ---- scatter: place src into dst's bucket.
//      Edge stream loaded evict-first so the bucket array stays L2-resident. ----
__global__ void k_scatter(const void* __restrict__ ei_raw, int E) {
    int e = blockIdx.x * TB + threadIdx.x;
    if (e >= E) return;
    int s, d;
    if (g_is64) {
        const long long* ei = (const long long*)ei_raw;
        s = (int)__ldcs(&ei[e]);
        d = (int)__ldcs(&ei[(long long)E + e]);
    } else {
        const int* ei = (const int*)ei_raw;
        s = __ldcs(&ei[e]);
        d = __ldcs(&ei[E + e]);
    }
    int p = atomicAdd(&g_cnt[d], 1);
    if (p < CAP)
        g_bsrc[(size_t)d * CAP + p] = s;
}

// ---- node init: pos4 pad + x0 = sp(pos@Wi + bi); xw = x0 @ W_g1 (fp16) ----
__global__ void k_node_init(const float* __restrict__ pos,
                            const float* __restrict__ Wi,
                            const float* __restrict__ bi,
                            const float* __restrict__ W1, int N) {
    __shared__ float sWi[48], sbi[16], sW1[256];
    int t = threadIdx.x;
    if (t < 48) sWi[t] = Wi[t];
    if (t < 16) sbi[t] = bi[t];
    sW1[t] = W1[t];
    __syncthreads();
    int n = blockIdx.x * TB + t;
    if (n >= N) return;
    float p0 = pos[3 * n + 0], p1 = pos[3 * n + 1], p2 = pos[3 * n + 2];
    g_pos4[n] = make_float4(p0, p1, p2, 0.0f);
    float x[16];
#pragma unroll
    for (int j = 0; j < 16; j++)
        x[j] = sp(fmaf(p0, sWi[j], fmaf(p1, sWi[16 + j], fmaf(p2, sWi[32 + j], sbi[j]))));
    float of[16];
#pragma unroll
    for (int j = 0; j < 16; j++) {
        float acc = 0.0f;
#pragma unroll
        for (int i = 0; i < 16; i++) acc = fmaf(x[i], sW1[i * 16 + j], acc);
        of[j] = acc;
    }
#pragma unroll
    for (int k = 0; k < 4; k++)
        g_xwh[n * 4 + k] = pack4h(of[4 * k], of[4 * k + 1], of[4 * k + 2], of[4 * k + 3]);
}

// ---- per node (quad): compute edge weights into g_bew (dense float4 stores),
//      weighted degree, dinv, scale xwh in place ----
__global__ void k_dinvscale(int N) {
    int tid = blockIdx.x * TB + threadIdx.x;
    int n = tid >> 2;
    int k = tid & 3;
    if (n >= N) return;                 // whole quads exit together
    size_t base = (size_t)n * CAP;
    int cnt = g_cnt[n];
    if (cnt > CAP) cnt = CAP;
    float4 pd = __ldg(&g_pos4[n]);
    const int4* s4 = (const int4*)&g_bsrc[base];   // base*4 = n*192, 16B aligned
    float4* e4 = (float4*)&g_bew[base];
    float s = 0.0f;
    int ngq = (cnt + 3) >> 2;           // groups of 4 edges
    for (int g = k; g < ngq; g += 4) {
        int4 ss = __ldg(&s4[g]);
        int rem = cnt - (g << 2);
        float4 ee = make_float4(0.0f, 0.0f, 0.0f, 0.0f);
        const int idx[4] = {ss.x, ss.y, ss.z, ss.w};
        float* ep = (float*)&ee;
#pragma unroll
        for (int j = 0; j < 4; j++) {
            if (j < rem) {
                float4 pa = __ldg(&g_pos4[idx[j]]);
                float ax = pa.x - pd.x, ay = pa.y - pd.y, az = pa.z - pd.z;
                float ew = sqrtf(ax * ax + ay * ay + az * az);
                ep[j] = ew;
                s += ew;
            }
        }
        e4[g] = ee;                     // dense 16B store
    }
    int lane = threadIdx.x & 31;
    unsigned mask = 0xFu << (lane & ~3);
    s += __shfl_xor_sync(mask, s, 1, 32);
    s += __shfl_xor_sync(mask, s, 2, 32);
    float dinv = rsqrtf(s + 1.0f);      // self-loop weight 1
    if (k == 0)
        g_df[n] = make_float2(dinv, dinv / (float)(cnt + 1));
    float4 v = unpack4h(g_xwh[n * 4 + k]);
    g_xwh[n * 4 + k] = pack4h(dinv * v.x, dinv * v.y, dinv * v.z, dinv * v.w);
}

// ---- aggregate + GCN finalize (4 threads per node). xwh holds dinv*xw.
//      LAST templates streaming loads for the final pass. ----
template <bool LAST>
__device__ __forceinline__ float4 agg_finalize(int n, int k, const float* sb) {
    size_t base = (size_t)n * CAP;
    int cnt = g_cnt[n];
    if (cnt > CAP) cnt = CAP;
    float4 acc = unpack4h(g_xwh[n * 4 + k]);   // self term (already dinv-scaled)
    const int4* s4 = (const int4*)&g_bsrc[base];
    const float4* e4 = (const float4*)&g_bew[base];
    int nq = cnt >> 2;
#pragma unroll 2
    for (int i = 0; i < nq; i++) {
        int4 ss = LAST ? __ldcs(&s4[i]) : __ldg(&s4[i]);
        float4 ee = LAST ? __ldcs(&e4[i]) : __ldg(&e4[i]);
        float4 v0 = unpack4h(__ldg(&g_xwh[ss.x * 4 + k]));
        float4 v1 = unpack4h(__ldg(&g_xwh[ss.y * 4 + k]));
        float4 v2 = unpack4h(__ldg(&g_xwh[ss.z * 4 + k]));
        float4 v3 = unpack4h(__ldg(&g_xwh[ss.w * 4 + k]));
        acc.x = fmaf(ee.x, v0.x, fmaf(ee.y, v1.x, fmaf(ee.z, v2.x, fmaf(ee.w, v3.x, acc.x))));
        acc.y = fmaf(ee.x, v0.y, fmaf(ee.y, v1.y, fmaf(ee.z, v2.y, fmaf(ee.w, v3.y, acc.y))));
        acc.z = fmaf(ee.x, v0.z, fmaf(ee.y, v1.z, fmaf(ee.z, v2.z, fmaf(ee.w, v3.z, acc.z))));
        acc.w = fmaf(ee.x, v0.w, fmaf(ee.y, v1.w, fmaf(ee.z, v2.w, fmaf(ee.w, v3.w, acc.w))));
    }
    for (int e = nq << 2; e < cnt; e++) {
        int src = __ldg(&g_bsrc[base + e]);
        float ew = __ldg(&g_bew[base + e]);
        float4 v = unpack4h(__ldg(&g_xwh[src * 4 + k]));
        acc.x = fmaf(ew, v.x, acc.x);
        acc.y = fmaf(ew, v.y, acc.y);
        acc.z = fmaf(ew, v.z, acc.z);
        acc.w = fmaf(ew, v.w, acc.w);
    }
    float f = __ldg(&g_df[n].y);               // dinv/(cnt+1)
    float4 x;
    x.x = sp(fmaf(f, acc.x, sb[4 * k + 0]));
    x.y = sp(fmaf(f, acc.y, sb[4 * k + 1]));
    x.z = sp(fmaf(f, acc.z, sb[4 * k + 2]));
    x.w = sp(fmaf(f, acc.w, sb[4 * k + 3]));
    return x;
}

// quad 16x16 matmul: x distributed 4 feats/thread -> o distributed 4/thread
__device__ __forceinline__ void quad_matmul(float4 x, const float* sW, int k,
                                            unsigned mask, int qbase, float o[4]) {
    o[0] = o[1] = o[2] = o[3] = 0.0f;
#pragma unroll
    for (int q = 0; q < 4; q++) {
        float4 xq;
        xq.x = __shfl_sync(mask, x.x, qbase + q, 32);
        xq.y = __shfl_sync(mask, x.y, qbase + q, 32);
        xq.z = __shfl_sync(mask, x.z, qbase + q, 32);
        xq.w = __shfl_sync(mask, x.w, qbase + q, 32);
        const float* w0 = &sW[(4 * q + 0) * 16 + 4 * k];
        const float* w1 = &sW[(4 * q + 1) * 16 + 4 * k];
        const float* w2 = &sW[(4 * q + 2) * 16 + 4 * k];
        const float* w3 = &sW[(4 * q + 3) * 16 + 4 * k];
#pragma unroll
        for (int j = 0; j < 4; j++) {
            o[j] = fmaf(xq.x, w0[j], o[j]);
            o[j] = fmaf(xq.y, w1[j], o[j]);
            o[j] = fmaf(xq.z, w2[j], o[j]);
            o[j] = fmaf(xq.w, w3[j], o[j]);
        }
    }
}

// ---- layer 1: aggregate + finalize + matmul W_g2, re-scale by dinv -> xwh ----
__global__ void k_agg1(const float* __restrict__ b1,
                       const float* __restrict__ W2, int N) {
    __shared__ float sb[16], sW[256];
    int t = threadIdx.x;
    if (t < 16) sb[t] = b1[t];
    sW[t] = W2[t];
    __syncthreads();
    int tid = blockIdx.x * TB + t;
    int n = tid >> 2;
    int k = tid & 3;
    if (n >= N) return;
    int lane = t & 31;
    int qbase = lane & ~3;
    unsigned mask = 0xFu << qbase;
    float4 x = agg_finalize<false>(n, k, sb);
    float o[4];
    quad_matmul(x, sW, k, mask, qbase, o);
    float dn = __ldg(&g_df[n].x);
    g_xwh[n * 4 + k] = pack4h(dn * o[0], dn * o[1], dn * o[2], dn * o[3]);
}

// ---- layer 2: aggregate + finalize + MLP (P1,sp,P2) + /sigma -> out ----
__global__ void k_agg2(const float* __restrict__ b2,
                       const float* __restrict__ Wp1,
                       const float* __restrict__ bp1,
                       const float* __restrict__ Wp2,
                       const float* __restrict__ bp2,
                       const float* __restrict__ sig,
                       float* __restrict__ out, int N) {
    __shared__ float sb2[16], sP1[256], sbp1[16], sP2[48], sbp2[3];
    int t = threadIdx.x;
    sP1[t] = Wp1[t];
    if (t < 16) { sb2[t] = b2[t]; sbp1[t] = bp1[t]; }
    if (t < 48) sP2[t] = Wp2[t];
    if (t < 3) sbp2[t] = bp2[t];
    __syncthreads();
    int tid = blockIdx.x * TB + t;
    int n = tid >> 2;
    int k = tid & 3;
    if (n >= N) return;
    int lane = t & 31;
    int qbase = lane & ~3;
    unsigned mask = 0xFu << qbase;
    float4 x = agg_finalize<true>(n, k, sb2);
    float o[4];
    quad_matmul(x, sP1, k, mask, qbase, o);
    float4 y;
    y.x = sp(o[0] + sbp1[4 * k + 0]);
    y.y = sp(o[1] + sbp1[4 * k + 1]);
    y.z = sp(o[2] + sbp1[4 * k + 2]);
    y.w = sp(o[3] + sbp1[4 * k + 3]);
    float sc[3];
#pragma unroll
    for (int j = 0; j < 3; j++) {
        sc[j] = y.x * sP2[(4 * k + 0) * 3 + j]
              + y.y * sP2[(4 * k + 1) * 3 + j]
              + y.z * sP2[(4 * k + 2) * 3 + j]
              + y.w * sP2[(4 * k + 3) * 3 + j];
    }
#pragma unroll
    for (int j = 0; j < 3; j++) {
        sc[j] += __shfl_xor_sync(mask, sc[j], 1, 32);
        sc[j] += __shfl_xor_sync(mask, sc[j], 2, 32);
    }
    if (k == 0) {
        float sgv = __ldg(&sig[n]);
        out[3 * n + 0] = (sc[0] + sbp2[0]) / sgv;
        out[3 * n + 1] = (sc[1] + sbp2[1]) / sgv;
        out[3 * n + 2] = (sc[2] + sbp2[2]) / sgv;
    }
}

extern "C" void kernel_launch(void* const* d_in, const int* in_sizes, int n_in,
                              void* d_out, int out_size) {
    const float* pos    = (const float*)d_in[0];
    const float* sigmas = (const float*)d_in[1];
    const void*  ei     = d_in[2];
    int wbase = (n_in >= 14 || (n_in > 3 && in_sizes[3] == 1)) ? 4 : 3;
    const float* W_init = (const float*)d_in[wbase + 0];
    const float* b_init = (const float*)d_in[wbase + 1];
    const float* W_g1   = (const float*)d_in[wbase + 2];
    const float* b_g1   = (const float*)d_in[wbase + 3];
    const float* W_g2   = (const float*)d_in[wbase + 4];
    const float* b_g2   = (const float*)d_in[wbase + 5];
    const float* W_p1   = (const float*)d_in[wbase + 6];
    const float* b_p1   = (const float*)d_in[wbase + 7];
    const float* W_p2   = (const float*)d_in[wbase + 8];
    const float* b_p2   = (const float*)d_in[wbase + 9];

    int N = in_sizes[0] / 3;
    if (N > MAXN) N = MAXN;
    int E = in_sizes[2] / 2;
    if (E > MAXE) E = MAXE;
    float* out = (float*)d_out;

    int nb_n = (N + TB - 1) / TB;
    int nb_e = (E + TB - 1) / TB;
    int nb_a = (4 * N + TB - 1) / TB;

    // side stream + events (created once on first, uncaptured correctness call)
    static cudaStream_t s2 = nullptr;
    static cudaEvent_t ev_fork = nullptr, ev_join = nullptr;
    if (!s2) {
        cudaStreamCreateWithFlags(&s2, cudaStreamNonBlocking);
        cudaEventCreateWithFlags(&ev_fork, cudaEventDisableTiming);
        cudaEventCreateWithFlags(&ev_join, cudaEventDisableTiming);
    }

    k_detect<<<1, 1>>>((const int*)ei);

    // fork immediately: node_init reads only pos (input) — overlaps edge chain
    cudaEventRecord(ev_fork, 0);
    cudaStreamWaitEvent(s2, ev_fork, 0);
    k_node_init<<<nb_n, TB, 0, s2>>>(pos, W_init, b_init, W_g1, N);
    cudaEventRecord(ev_join, s2);

    // edge chain on main stream
    k_zero<<<nb_n, TB>>>(N);
    k_scatter<<<nb_e, TB>>>(ei, E);

    // join: dinvscale needs buckets (main) and xwh+pos4 (side)
    cudaStreamWaitEvent(0, ev_join, 0);
    k_dinvscale<<<nb_a, TB>>>(N);
    k_agg1<<<nb_a, TB>>>(b_g1, W_g2, N);
    k_agg2<<<nb_a, TB>>>(b_g2, W_p1, b_p1, W_p2, b_p2, sigmas, out, N);
}